// round 16
// baseline (speedup 1.0000x reference)
#include <cuda_runtime.h>
#include <cuda_bf16.h>
#include <cstdint>

#define B_    2
#define NPIX  6400
#define D     128
#define CHSI  128
#define CMSI  64
#define COUT  128
#define NTHR  256

#define TI    128
#define TJ    64
#define SPLIT 4
#define JPC   (NPIX/SPLIT)   // 1600
#define TJT   (JPC/TJ)       // 25
#define NIT   (NPIX/TI)      // 50

#define LOG2E 1.4426950408889634f
#define ZST   72

// ---- smem byte offsets (attn, all bf16) ----
#define SQ   0
#define SK0  32768
#define SK1  (SK0 + 16384)
#define SV0  (SK1 + 16384)
#define SV1  (SV0 + 16384)
#define SM_TOTAL (SV1 + 16384)   // 98304 -> 2 CTAs/SM

// ---- scratch ----
__device__ __nv_bfloat16 g_Qh [B_ * NPIX * D];   // [b][n][d]  (pre-scaled by log2e)
__device__ __nv_bfloat16 g_Kh [B_ * NPIX * D];   // [b][n][d]
__device__ __nv_bfloat16 g_Vth[B_ * D * NPIX];   // [b][d][n]
__device__ float g_Op[B_ * NIT * SPLIT * TI * D];
__device__ float g_lp[B_ * NIT * SPLIT * TI];

// ======================= helpers =======================
__device__ __forceinline__ uint32_t smem_to_u32(const void* p) {
    uint32_t a;
    asm("{ .reg .u64 t; cvta.to.shared.u64 t, %1; cvt.u32.u64 %0, t; }" : "=r"(a) : "l"(p));
    return a;
}
__device__ __forceinline__ void cp16(uint32_t dst, const void* src) {
    asm volatile("cp.async.cg.shared.global [%0], [%1], 16;" :: "r"(dst), "l"(src));
}
#define CP_COMMIT() asm volatile("cp.async.commit_group;" ::: "memory")
#define CP_WAIT0()  asm volatile("cp.async.wait_group 0;" ::: "memory")
#define CP_WAIT1()  asm volatile("cp.async.wait_group 1;" ::: "memory")

__device__ __forceinline__ uint32_t pk2(float lo, float hi) {
    __nv_bfloat162 h = __float22bfloat162_rn(make_float2(lo, hi));
    return *(uint32_t*)&h;
}
__device__ __forceinline__ float ex2(float x) {
    float r; asm("ex2.approx.f32 %0, %1;" : "=f"(r) : "f"(x)); return r;
}
__device__ __forceinline__ void ldsm4(uint32_t* r, uint32_t addr) {
    asm volatile("ldmatrix.sync.aligned.m8n8.x4.shared.b16 {%0,%1,%2,%3}, [%4];"
        : "=r"(r[0]), "=r"(r[1]), "=r"(r[2]), "=r"(r[3]) : "r"(addr));
}
__device__ __forceinline__ void mma16(float* d, const uint32_t* a, const uint32_t* b) {
    asm volatile(
        "mma.sync.aligned.m16n8k16.row.col.f32.bf16.bf16.f32 "
        "{%0,%1,%2,%3}, {%4,%5,%6,%7}, {%8,%9}, {%0,%1,%2,%3};"
        : "+f"(d[0]), "+f"(d[1]), "+f"(d[2]), "+f"(d[3])
        : "r"(a[0]), "r"(a[1]), "r"(a[2]), "r"(a[3]), "r"(b[0]), "r"(b[1]));
}
__device__ __forceinline__ void mma8(float* d, const uint32_t* a, const uint32_t* b) {
    asm volatile(
        "mma.sync.aligned.m16n8k8.row.col.f32.tf32.tf32.f32 "
        "{%0,%1,%2,%3}, {%4,%5,%6,%7}, {%8,%9}, {%0,%1,%2,%3};"
        : "+f"(d[0]), "+f"(d[1]), "+f"(d[2]), "+f"(d[3])
        : "r"(a[0]), "r"(a[1]), "r"(a[2]), "r"(a[3]), "r"(b[0]), "r"(b[1]));
}

__device__ __forceinline__ void cp_qk(uint32_t dst, const char* src, int nchunks, int tid) {
    for (int id = tid; id < nchunks; id += NTHR) {
        int r = id >> 4, c = id & 15;
        cp16(dst + r * 256 + ((c ^ (r & 7)) << 4), src + r * 256 + c * 16);
    }
}
__device__ __forceinline__ void cp_v(uint32_t dst, const char* src, int tid) {
    for (int id = tid; id < 1024; id += NTHR) {
        int r = id >> 3, c = id & 7;
        cp16(dst + r * 128 + ((c ^ (r & 7)) << 4), src + (size_t)r * (NPIX * 2) + c * 16);
    }
}

// ======================= tf32 tensor-core projection bodies =======================
template <int CIN>
__device__ __forceinline__ void proj_qk_body(
    const float* __restrict__ zs, const float* __restrict__ Ws,
    const float* __restrict__ bias, __nv_bfloat16* __restrict__ outp,
    float scale, int b, int n0, int wid, int lr, int q)
{
    constexpr int WST = CIN + 8;
    const int pxb = (wid & 1) * 32;
    const int ob  = (wid >> 1) * 32;

    float dd[32];
#pragma unroll
    for (int n = 0; n < 4; n++) {
        float b0v = __ldg(bias + ob + 8 * n + 2 * q);
        float b1v = __ldg(bias + ob + 8 * n + 2 * q + 1);
#pragma unroll
        for (int m = 0; m < 2; m++) {
            dd[(m * 4 + n) * 4 + 0] = b0v; dd[(m * 4 + n) * 4 + 1] = b1v;
            dd[(m * 4 + n) * 4 + 2] = b0v; dd[(m * 4 + n) * 4 + 3] = b1v;
        }
    }
#pragma unroll 4
    for (int k0 = 0; k0 < CIN; k0 += 8) {
        uint32_t a[2][4];
#pragma unroll
        for (int m = 0; m < 2; m++) {
            const int px = pxb + 16 * m + lr;
            a[m][0] = __float_as_uint(zs[(k0 + q    ) * ZST + px    ]);
            a[m][1] = __float_as_uint(zs[(k0 + q    ) * ZST + px + 8]);
            a[m][2] = __float_as_uint(zs[(k0 + q + 4) * ZST + px    ]);
            a[m][3] = __float_as_uint(zs[(k0 + q + 4) * ZST + px + 8]);
        }
        uint32_t bb[4][2];
#pragma unroll
        for (int n = 0; n < 4; n++) {
            const int o = ob + 8 * n + lr;
            bb[n][0] = __float_as_uint(Ws[o * WST + k0 + q]);
            bb[n][1] = __float_as_uint(Ws[o * WST + k0 + q + 4]);
        }
#pragma unroll
        for (int n = 0; n < 4; n++) {
            mma8(dd + (0 * 4 + n) * 4, a[0], bb[n]);
            mma8(dd + (1 * 4 + n) * 4, a[1], bb[n]);
        }
    }
#pragma unroll
    for (int m = 0; m < 2; m++) {
        const int px = pxb + 16 * m + lr;
#pragma unroll
        for (int n = 0; n < 4; n++) {
            const int o = ob + 8 * n + 2 * q;
            float* dp = dd + (m * 4 + n) * 4;
            *(uint32_t*)(outp + ((size_t)(b * NPIX + n0 + px    )) * COUT + o)
                = pk2(dp[0] * scale, dp[1] * scale);
            *(uint32_t*)(outp + ((size_t)(b * NPIX + n0 + px + 8)) * COUT + o)
                = pk2(dp[2] * scale, dp[3] * scale);
        }
    }
}

template <int CIN>
__device__ __forceinline__ void proj_v_body(
    const float* __restrict__ zs, const float* __restrict__ Ws,
    const float* __restrict__ bias, __nv_bfloat16* __restrict__ outp,
    int b, int n0, int wid, int lr, int q)
{
    constexpr int WST = CIN + 8;
    const int o2b  = (wid & 3) * 32;
    const int px2b = (wid >> 2) * 32;

    float dv[32];
#pragma unroll
    for (int m = 0; m < 2; m++) {
        float bv0 = __ldg(bias + o2b + 16 * m + lr);
        float bv8 = __ldg(bias + o2b + 16 * m + lr + 8);
#pragma unroll
        for (int n = 0; n < 4; n++) {
            dv[(m * 4 + n) * 4 + 0] = bv0; dv[(m * 4 + n) * 4 + 1] = bv0;
            dv[(m * 4 + n) * 4 + 2] = bv8; dv[(m * 4 + n) * 4 + 3] = bv8;
        }
    }
#pragma unroll 4
    for (int k0 = 0; k0 < CIN; k0 += 8) {
        uint32_t a[2][4];
#pragma unroll
        for (int m = 0; m < 2; m++) {
            const int o = o2b + 16 * m + lr;
            a[m][0] = __float_as_uint(Ws[(o    ) * WST + k0 + q]);
            a[m][1] = __float_as_uint(Ws[(o + 8) * WST + k0 + q]);
            a[m][2] = __float_as_uint(Ws[(o    ) * WST + k0 + q + 4]);
            a[m][3] = __float_as_uint(Ws[(o + 8) * WST + k0 + q + 4]);
        }
        uint32_t bb[4][2];
#pragma unroll
        for (int n = 0; n < 4; n++) {
            const int px = px2b + 8 * n + lr;
            bb[n][0] = __float_as_uint(zs[(k0 + q    ) * ZST + px]);
            bb[n][1] = __float_as_uint(zs[(k0 + q + 4) * ZST + px]);
        }
#pragma unroll
        for (int n = 0; n < 4; n++) {
            mma8(dv + (0 * 4 + n) * 4, a[0], bb[n]);
            mma8(dv + (1 * 4 + n) * 4, a[1], bb[n]);
        }
    }
#pragma unroll
    for (int m = 0; m < 2; m++) {
        const int o = o2b + 16 * m + lr;
#pragma unroll
        for (int n = 0; n < 4; n++) {
            const int px = px2b + 8 * n + 2 * q;
            float* dp = dv + (m * 4 + n) * 4;
            *(uint32_t*)(outp + ((size_t)b * D + o    ) * NPIX + n0 + px) = pk2(dp[0], dp[1]);
            *(uint32_t*)(outp + ((size_t)b * D + o + 8) * NPIX + n0 + px) = pk2(dp[2], dp[3]);
        }
    }
}

// Fused projection: grid (200, 2). y=0: Q. y=1: K and V sharing staged z_msi.
__global__ void __launch_bounds__(NTHR)
proj_fused(const float* __restrict__ zhsi, const float* __restrict__ Wq,
           const float* __restrict__ bq,   const float* __restrict__ zmsi,
           const float* __restrict__ Wk,   const float* __restrict__ bk,
           const float* __restrict__ Wv,   const float* __restrict__ bv,
           __nv_bfloat16* __restrict__ Qo, __nv_bfloat16* __restrict__ Ko,
           __nv_bfloat16* __restrict__ Vto)
{
    extern __shared__ float sm[];
    const int tid = threadIdx.x;
    const int nb  = NPIX / 64;
    const int b   = blockIdx.x / nb;
    const int n0  = (blockIdx.x % nb) * 64;
    const int wid  = tid >> 5;
    const int lane = tid & 31;
    const int lr   = lane >> 2;
    const int q    = lane & 3;

    if (blockIdx.y == 0) {
        constexpr int WST = CHSI + 8;
        float* zs = sm;
        float* Ws = sm + CHSI * ZST;
        const uint32_t zsb = smem_to_u32(zs);
        const uint32_t wsb = smem_to_u32(Ws);
        const float* zb = zhsi + (size_t)b * CHSI * NPIX + n0;
        for (int id = tid; id < CHSI * 16; id += NTHR) {
            int r = id >> 4, c = id & 15;
            cp16(zsb + r * (ZST * 4) + c * 16, zb + (size_t)r * NPIX + c * 4);
        }
        for (int id = tid; id < COUT * (CHSI / 4); id += NTHR) {
            int r = id / (CHSI / 4), c = id % (CHSI / 4);
            cp16(wsb + r * (WST * 4) + c * 16, Wq + (size_t)r * CHSI + c * 4);
        }
        CP_COMMIT(); CP_WAIT0();
        __syncthreads();
        proj_qk_body<CHSI>(zs, Ws, bq, Qo, LOG2E, b, n0, wid, lr, q);
    } else {
        constexpr int WST = CMSI + 8;
        float* zs  = sm;
        float* Wks = sm + CMSI * ZST;
        float* Wvs = Wks + COUT * WST;
        const uint32_t zsb = smem_to_u32(zs);
        const uint32_t wkb = smem_to_u32(Wks);
        const uint32_t wvb = smem_to_u32(Wvs);
        const float* zb = zmsi + (size_t)b * CMSI * NPIX + n0;
        for (int id = tid; id < CMSI * 16; id += NTHR) {
            int r = id >> 4, c = id & 15;
            cp16(zsb + r * (ZST * 4) + c * 16, zb + (size_t)r * NPIX + c * 4);
        }
        for (int id = tid; id < COUT * (CMSI / 4); id += NTHR) {
            int r = id / (CMSI / 4), c = id % (CMSI / 4);
            cp16(wkb + r * (WST * 4) + c * 16, Wk + (size_t)r * CMSI + c * 4);
            cp16(wvb + r * (WST * 4) + c * 16, Wv + (size_t)r * CMSI + c * 4);
        }
        CP_COMMIT(); CP_WAIT0();
        __syncthreads();
        proj_qk_body<CMSI>(zs, Wks, bk, Ko, 1.0f, b, n0, wid, lr, q);
        proj_v_body<CMSI>(zs, Wvs, bv, Vto, b, n0, wid, lr, q);
    }
}

// ======================= bf16 mma flash attention (fused exp->MMA2 per k-quarter) =======================
__global__ void __launch_bounds__(NTHR, 2)
attn_mma()
{
    extern __shared__ char smem[];
    const uint32_t sb = smem_to_u32(smem);
    const int tid  = threadIdx.x;
    const int wid  = tid >> 5;
    const int lane = tid & 31;
    const int lr   = lane >> 2;
    const int q    = lane & 3;

    const int bi = blockIdx.x;
    const int s  = bi % SPLIT;
    const int it = (bi / SPLIT) % NIT;
    const int b  = bi / (SPLIT * NIT);
    const int i0 = it * TI;
    const int jb = s * JPC;

    const char* Qg = (const char*)(g_Qh  + ((size_t)b * NPIX + i0) * D);
    const char* Kg = (const char*)(g_Kh  + (size_t)b * NPIX * D);
    const char* Vg = (const char*)(g_Vth + (size_t)b * D * NPIX);

    cp_qk(sb + SQ,  Qg, 2048, tid);
    cp_qk(sb + SK0, Kg + (size_t)jb * 256, 1024, tid);
    cp_v (sb + SV0, Vg + (size_t)jb * 2, tid);
    CP_COMMIT();
    cp_qk(sb + SK1, Kg + (size_t)(jb + TJ) * 256, 1024, tid);
    cp_v (sb + SV1, Vg + (size_t)(jb + TJ) * 2, tid);
    CP_COMMIT();

    float oacc[64];
#pragma unroll
    for (int i = 0; i < 64; i++) oacc[i] = 0.f;
    float l0 = 0.f, l1 = 0.f;

    const int rowbase = wid * 16;
    const int s8   = lane >> 3;
    const int r8   = lane & 7;
    const int s_lo = s8 & 1;
    const int s_hi = s8 >> 1;

    const uint32_t qbase = sb + SQ + (uint32_t)(rowbase + s_lo * 8 + r8) * 256;
    const uint32_t kbase = (uint32_t)(s_hi * 8 + r8) * 256;
    const uint32_t vbase = (uint32_t)(s_hi * 8 + r8) * 128;

    for (int t = 0; t < TJT; t++) {
        if (t == TJT - 1) CP_WAIT0(); else CP_WAIT1();
        __syncthreads();
        const uint32_t skb = sb + ((t & 1) ? SK1 : SK0) + kbase;
        const uint32_t svb = sb + ((t & 1) ? SV1 : SV0) + vbase;

        // ---- MMA1: rows[rowbase,+16) x keys[0,64), 8 k16 steps ----
        float sacc[32];
#pragma unroll
        for (int i = 0; i < 32; i++) sacc[i] = 0.f;

#pragma unroll
        for (int kk = 0; kk < 8; kk++) {
            const uint32_t ca = (uint32_t)((2 * kk + s_hi) ^ r8) << 4;
            const uint32_t cb = (uint32_t)((2 * kk + s_lo) ^ r8) << 4;
            uint32_t A[4];
            ldsm4(A, qbase + ca);
#pragma unroll
            for (int g = 0; g < 4; g++) {
                uint32_t B[4];
                ldsm4(B, skb + (uint32_t)g * 4096 + cb);
                mma16(sacc + (2 * g) * 4,     A, B);
                mma16(sacc + (2 * g + 1) * 4, A, B + 2);
            }
        }

        // ---- fused: per k-quarter, exp2 -> pack -> MMA2 (shortens critical path) ----
#pragma unroll
        for (int kk = 0; kk < 4; kk++) {
            float* sp = sacc + 8 * kk;
            float e0 = ex2(sp[0]);
            float e1 = ex2(sp[1]);
            float e2 = ex2(sp[2]);
            float e3 = ex2(sp[3]);
            float e4 = ex2(sp[4]);
            float e5 = ex2(sp[5]);
            float e6 = ex2(sp[6]);
            float e7 = ex2(sp[7]);
            l0 += e0 + e1; l1 += e2 + e3;
            l0 += e4 + e5; l1 += e6 + e7;
            uint32_t A[4];
            A[0] = pk2(e0, e1);
            A[1] = pk2(e2, e3);
            A[2] = pk2(e4, e5);
            A[3] = pk2(e6, e7);
            const uint32_t cb = (uint32_t)((2 * kk + s_lo) ^ r8) << 4;
#pragma unroll
            for (int g = 0; g < 8; g++) {
                uint32_t B[4];
                ldsm4(B, svb + (uint32_t)g * 2048 + cb);
                mma16(oacc + (2 * g) * 4,     A, B);
                mma16(oacc + (2 * g + 1) * 4, A, B + 2);
            }
        }
        __syncthreads();

        if (t + 2 < TJT) {
            const int jn = jb + (t + 2) * TJ;
            cp_qk(((t & 1) ? sb + SK1 : sb + SK0), Kg + (size_t)jn * 256, 1024, tid);
            cp_v (((t & 1) ? sb + SV1 : sb + SV0), Vg + (size_t)jn * 2, tid);
            CP_COMMIT();
        }
    }

    l0 += __shfl_xor_sync(0xffffffffu, l0, 1);
    l0 += __shfl_xor_sync(0xffffffffu, l0, 2);
    l1 += __shfl_xor_sync(0xffffffffu, l1, 1);
    l1 += __shfl_xor_sync(0xffffffffu, l1, 2);
    if (q == 0) {
        g_lp[(size_t)bi * TI + rowbase + lr]     = l0;
        g_lp[(size_t)bi * TI + rowbase + lr + 8] = l1;
    }
#pragma unroll
    for (int nn = 0; nn < 16; nn++) {
        const int c = nn * 8 + 2 * q;
        const int row0 = rowbase + lr;
        *(float2*)(g_Op + ((size_t)bi * TI + row0) * D + c) =
            make_float2(oacc[nn * 4 + 0], oacc[nn * 4 + 1]);
        *(float2*)(g_Op + ((size_t)bi * TI + row0 + 8) * D + c) =
            make_float2(oacc[nn * 4 + 2], oacc[nn * 4 + 3]);
    }
}

// ======================= split combine (unchanged) =======================
__global__ void __launch_bounds__(NTHR)
combine_kernel(const float* __restrict__ zhsi, const float* __restrict__ gammap,
               float* __restrict__ outp)
{
    __shared__ float sacc[32 * 129];
    __shared__ float rinv[TI];

    const int part = blockIdx.x & 3;
    const int blk  = blockIdx.x >> 2;
    const int b  = blk / NIT;
    const int i0 = (blk % NIT) * TI;
    const float g = *gammap;
    const int base = blk * SPLIT;
    const int tid = threadIdx.x;

    if (tid < TI) {
        float sl = 0.f;
#pragma unroll
        for (int sp = 0; sp < SPLIT; sp++)
            sl += g_lp[(size_t)(base + sp) * TI + tid];
        rinv[tid] = 1.0f / sl;
    }

#pragma unroll
    for (int k = 0; k < 4; k++) {
        const int f  = tid + NTHR * k;
        const int r  = f >> 3;
        const int c4 = f & 7;
        float4 a = make_float4(0.f, 0.f, 0.f, 0.f);
#pragma unroll
        for (int sp = 0; sp < SPLIT; sp++) {
            const float4* src = (const float4*)(g_Op
                + ((size_t)(base + sp) * TI + r) * D + part * 32);
            float4 v = __ldg(src + c4);
            a.x += v.x; a.y += v.y; a.z += v.z; a.w += v.w;
        }
        const int c = c4 * 4;
        sacc[(c + 0) * 129 + r] = a.x;
        sacc[(c + 1) * 129 + r] = a.y;
        sacc[(c + 2) * 129 + r] = a.z;
        sacc[(c + 3) * 129 + r] = a.w;
    }
    __syncthreads();

    for (int idx = tid; idx < 32 * TI; idx += NTHR) {
        const int c = idx >> 7;
        const int r = idx & 127;
        const size_t o = ((size_t)b * D + part * 32 + c) * NPIX + i0 + r;
        outp[o] = g * sacc[c * 129 + r] * rinv[r] + zhsi[o];
    }
}

// ======================= launch =======================
extern "C" void kernel_launch(void* const* d_in, const int* in_sizes, int n_in,
                              void* d_out, int out_size)
{
    const float* z_hsi = (const float*)d_in[0];
    const float* z_msi = (const float*)d_in[1];
    const float* Wq    = (const float*)d_in[2];
    const float* bq    = (const float*)d_in[3];
    const float* Wk    = (const float*)d_in[4];
    const float* bk    = (const float*)d_in[5];
    const float* Wv    = (const float*)d_in[6];
    const float* bv    = (const float*)d_in[7];
    const float* gamma = (const float*)d_in[8];
    float* out = (float*)d_out;

    __nv_bfloat16 *Qp, *Kp, *Vp;
    cudaGetSymbolAddress((void**)&Qp, g_Qh);
    cudaGetSymbolAddress((void**)&Kp, g_Kh);
    cudaGetSymbolAddress((void**)&Vp, g_Vth);

    const int smem_proj = (CHSI * ZST + COUT * (CHSI + 8)) * 4;  // 106496

    cudaFuncSetAttribute(proj_fused,
                         cudaFuncAttributeMaxDynamicSharedMemorySize, smem_proj);
    cudaFuncSetAttribute(attn_mma,
                         cudaFuncAttributeMaxDynamicSharedMemorySize, SM_TOTAL);

    dim3 pg(B_ * (NPIX / 64), 2);   // (200, 2)
    proj_fused<<<pg, NTHR, smem_proj>>>(z_hsi, Wq, bq, z_msi, Wk, bk, Wv, bv,
                                        Qp, Kp, Vp);

    attn_mma<<<B_ * NIT * SPLIT, NTHR, SM_TOTAL>>>();

    combine_kernel<<<B_ * NIT * 4, NTHR>>>(z_hsi, gamma, out);
}

// round 17
// speedup vs baseline: 1.0259x; 1.0259x over previous
#include <cuda_runtime.h>
#include <cuda_bf16.h>
#include <cstdint>

#define B_    2
#define NPIX  6400
#define D     128
#define CHSI  128
#define CMSI  64
#define COUT  128
#define NTHR  256

#define TI    128
#define TJ    64
#define SPLIT 4
#define JPC   (NPIX/SPLIT)   // 1600
#define TJT   (JPC/TJ)       // 25
#define NIT   (NPIX/TI)      // 50

#define LOG2E 1.4426950408889634f
#define ZST   72

// ---- smem byte offsets (attn, all bf16) ----
#define SQ   0
#define SK0  32768
#define SK1  (SK0 + 16384)
#define SV0  (SK1 + 16384)
#define SV1  (SV0 + 16384)
#define SM_TOTAL (SV1 + 16384)   // 98304 -> 2 CTAs/SM

// ---- scratch ----
__device__ __nv_bfloat16 g_Qh [B_ * NPIX * D];   // [b][n][d]  (pre-scaled by log2e)
__device__ __nv_bfloat16 g_Kh [B_ * NPIX * D];   // [b][n][d]
__device__ __nv_bfloat16 g_Vth[B_ * D * NPIX];   // [b][d][n]
__device__ float g_Op[B_ * NIT * SPLIT * TI * D];
__device__ float g_lp[B_ * NIT * SPLIT * TI];

// ======================= helpers =======================
__device__ __forceinline__ uint32_t smem_to_u32(const void* p) {
    uint32_t a;
    asm("{ .reg .u64 t; cvta.to.shared.u64 t, %1; cvt.u32.u64 %0, t; }" : "=r"(a) : "l"(p));
    return a;
}
__device__ __forceinline__ void cp16(uint32_t dst, const void* src) {
    asm volatile("cp.async.cg.shared.global [%0], [%1], 16;" :: "r"(dst), "l"(src));
}
#define CP_COMMIT() asm volatile("cp.async.commit_group;" ::: "memory")
#define CP_WAIT0()  asm volatile("cp.async.wait_group 0;" ::: "memory")
#define CP_WAIT1()  asm volatile("cp.async.wait_group 1;" ::: "memory")

__device__ __forceinline__ uint32_t pk2(float lo, float hi) {
    __nv_bfloat162 h = __float22bfloat162_rn(make_float2(lo, hi));
    return *(uint32_t*)&h;
}
__device__ __forceinline__ float ex2(float x) {
    float r; asm("ex2.approx.f32 %0, %1;" : "=f"(r) : "f"(x)); return r;
}
__device__ __forceinline__ void ldsm4(uint32_t* r, uint32_t addr) {
    asm volatile("ldmatrix.sync.aligned.m8n8.x4.shared.b16 {%0,%1,%2,%3}, [%4];"
        : "=r"(r[0]), "=r"(r[1]), "=r"(r[2]), "=r"(r[3]) : "r"(addr));
}
__device__ __forceinline__ void mma16(float* d, const uint32_t* a, const uint32_t* b) {
    asm volatile(
        "mma.sync.aligned.m16n8k16.row.col.f32.bf16.bf16.f32 "
        "{%0,%1,%2,%3}, {%4,%5,%6,%7}, {%8,%9}, {%0,%1,%2,%3};"
        : "+f"(d[0]), "+f"(d[1]), "+f"(d[2]), "+f"(d[3])
        : "r"(a[0]), "r"(a[1]), "r"(a[2]), "r"(a[3]), "r"(b[0]), "r"(b[1]));
}
__device__ __forceinline__ void mma8(float* d, const uint32_t* a, const uint32_t* b) {
    asm volatile(
        "mma.sync.aligned.m16n8k8.row.col.f32.tf32.tf32.f32 "
        "{%0,%1,%2,%3}, {%4,%5,%6,%7}, {%8,%9}, {%0,%1,%2,%3};"
        : "+f"(d[0]), "+f"(d[1]), "+f"(d[2]), "+f"(d[3])
        : "r"(a[0]), "r"(a[1]), "r"(a[2]), "r"(a[3]), "r"(b[0]), "r"(b[1]));
}

__device__ __forceinline__ void cp_qk(uint32_t dst, const char* src, int nchunks, int tid) {
    for (int id = tid; id < nchunks; id += NTHR) {
        int r = id >> 4, c = id & 15;
        cp16(dst + r * 256 + ((c ^ (r & 7)) << 4), src + r * 256 + c * 16);
    }
}
__device__ __forceinline__ void cp_v(uint32_t dst, const char* src, int tid) {
    for (int id = tid; id < 1024; id += NTHR) {
        int r = id >> 3, c = id & 7;
        cp16(dst + r * 128 + ((c ^ (r & 7)) << 4), src + (size_t)r * (NPIX * 2) + c * 16);
    }
}

// ======================= tf32 tensor-core projection bodies =======================
template <int CIN>
__device__ __forceinline__ void proj_qk_body(
    const float* __restrict__ zs, const float* __restrict__ Ws,
    const float* __restrict__ bias, __nv_bfloat16* __restrict__ outp,
    float scale, int b, int n0, int wid, int lr, int q)
{
    constexpr int WST = CIN + 8;
    const int pxb = (wid & 1) * 32;
    const int ob  = (wid >> 1) * 32;

    float dd[32];
#pragma unroll
    for (int n = 0; n < 4; n++) {
        float b0v = __ldg(bias + ob + 8 * n + 2 * q);
        float b1v = __ldg(bias + ob + 8 * n + 2 * q + 1);
#pragma unroll
        for (int m = 0; m < 2; m++) {
            dd[(m * 4 + n) * 4 + 0] = b0v; dd[(m * 4 + n) * 4 + 1] = b1v;
            dd[(m * 4 + n) * 4 + 2] = b0v; dd[(m * 4 + n) * 4 + 3] = b1v;
        }
    }
#pragma unroll 4
    for (int k0 = 0; k0 < CIN; k0 += 8) {
        uint32_t a[2][4];
#pragma unroll
        for (int m = 0; m < 2; m++) {
            const int px = pxb + 16 * m + lr;
            a[m][0] = __float_as_uint(zs[(k0 + q    ) * ZST + px    ]);
            a[m][1] = __float_as_uint(zs[(k0 + q    ) * ZST + px + 8]);
            a[m][2] = __float_as_uint(zs[(k0 + q + 4) * ZST + px    ]);
            a[m][3] = __float_as_uint(zs[(k0 + q + 4) * ZST + px + 8]);
        }
        uint32_t bb[4][2];
#pragma unroll
        for (int n = 0; n < 4; n++) {
            const int o = ob + 8 * n + lr;
            bb[n][0] = __float_as_uint(Ws[o * WST + k0 + q]);
            bb[n][1] = __float_as_uint(Ws[o * WST + k0 + q + 4]);
        }
#pragma unroll
        for (int n = 0; n < 4; n++) {
            mma8(dd + (0 * 4 + n) * 4, a[0], bb[n]);
            mma8(dd + (1 * 4 + n) * 4, a[1], bb[n]);
        }
    }
#pragma unroll
    for (int m = 0; m < 2; m++) {
        const int px = pxb + 16 * m + lr;
#pragma unroll
        for (int n = 0; n < 4; n++) {
            const int o = ob + 8 * n + 2 * q;
            float* dp = dd + (m * 4 + n) * 4;
            *(uint32_t*)(outp + ((size_t)(b * NPIX + n0 + px    )) * COUT + o)
                = pk2(dp[0] * scale, dp[1] * scale);
            *(uint32_t*)(outp + ((size_t)(b * NPIX + n0 + px + 8)) * COUT + o)
                = pk2(dp[2] * scale, dp[3] * scale);
        }
    }
}

template <int CIN>
__device__ __forceinline__ void proj_v_body(
    const float* __restrict__ zs, const float* __restrict__ Ws,
    const float* __restrict__ bias, __nv_bfloat16* __restrict__ outp,
    int b, int n0, int wid, int lr, int q)
{
    constexpr int WST = CIN + 8;
    const int o2b  = (wid & 3) * 32;
    const int px2b = (wid >> 2) * 32;

    float dv[32];
#pragma unroll
    for (int m = 0; m < 2; m++) {
        float bv0 = __ldg(bias + o2b + 16 * m + lr);
        float bv8 = __ldg(bias + o2b + 16 * m + lr + 8);
#pragma unroll
        for (int n = 0; n < 4; n++) {
            dv[(m * 4 + n) * 4 + 0] = bv0; dv[(m * 4 + n) * 4 + 1] = bv0;
            dv[(m * 4 + n) * 4 + 2] = bv8; dv[(m * 4 + n) * 4 + 3] = bv8;
        }
    }
#pragma unroll 4
    for (int k0 = 0; k0 < CIN; k0 += 8) {
        uint32_t a[2][4];
#pragma unroll
        for (int m = 0; m < 2; m++) {
            const int o = o2b + 16 * m + lr;
            a[m][0] = __float_as_uint(Ws[(o    ) * WST + k0 + q]);
            a[m][1] = __float_as_uint(Ws[(o + 8) * WST + k0 + q]);
            a[m][2] = __float_as_uint(Ws[(o    ) * WST + k0 + q + 4]);
            a[m][3] = __float_as_uint(Ws[(o + 8) * WST + k0 + q + 4]);
        }
        uint32_t bb[4][2];
#pragma unroll
        for (int n = 0; n < 4; n++) {
            const int px = px2b + 8 * n + lr;
            bb[n][0] = __float_as_uint(zs[(k0 + q    ) * ZST + px]);
            bb[n][1] = __float_as_uint(zs[(k0 + q + 4) * ZST + px]);
        }
#pragma unroll
        for (int n = 0; n < 4; n++) {
            mma8(dv + (0 * 4 + n) * 4, a[0], bb[n]);
            mma8(dv + (1 * 4 + n) * 4, a[1], bb[n]);
        }
    }
#pragma unroll
    for (int m = 0; m < 2; m++) {
        const int o = o2b + 16 * m + lr;
#pragma unroll
        for (int n = 0; n < 4; n++) {
            const int px = px2b + 8 * n + 2 * q;
            float* dp = dv + (m * 4 + n) * 4;
            *(uint32_t*)(outp + ((size_t)b * D + o    ) * NPIX + n0 + px) = pk2(dp[0], dp[1]);
            *(uint32_t*)(outp + ((size_t)b * D + o + 8) * NPIX + n0 + px) = pk2(dp[2], dp[3]);
        }
    }
}

// Fused projection: grid (200, 2). y=0: Q. y=1: K and V sharing staged z_msi.
__global__ void __launch_bounds__(NTHR)
proj_fused(const float* __restrict__ zhsi, const float* __restrict__ Wq,
           const float* __restrict__ bq,   const float* __restrict__ zmsi,
           const float* __restrict__ Wk,   const float* __restrict__ bk,
           const float* __restrict__ Wv,   const float* __restrict__ bv,
           __nv_bfloat16* __restrict__ Qo, __nv_bfloat16* __restrict__ Ko,
           __nv_bfloat16* __restrict__ Vto)
{
    extern __shared__ float sm[];
    const int tid = threadIdx.x;
    const int nb  = NPIX / 64;
    const int b   = blockIdx.x / nb;
    const int n0  = (blockIdx.x % nb) * 64;
    const int wid  = tid >> 5;
    const int lane = tid & 31;
    const int lr   = lane >> 2;
    const int q    = lane & 3;

    if (blockIdx.y == 0) {
        constexpr int WST = CHSI + 8;
        float* zs = sm;
        float* Ws = sm + CHSI * ZST;
        const uint32_t zsb = smem_to_u32(zs);
        const uint32_t wsb = smem_to_u32(Ws);
        const float* zb = zhsi + (size_t)b * CHSI * NPIX + n0;
        for (int id = tid; id < CHSI * 16; id += NTHR) {
            int r = id >> 4, c = id & 15;
            cp16(zsb + r * (ZST * 4) + c * 16, zb + (size_t)r * NPIX + c * 4);
        }
        for (int id = tid; id < COUT * (CHSI / 4); id += NTHR) {
            int r = id / (CHSI / 4), c = id % (CHSI / 4);
            cp16(wsb + r * (WST * 4) + c * 16, Wq + (size_t)r * CHSI + c * 4);
        }
        CP_COMMIT(); CP_WAIT0();
        __syncthreads();
        proj_qk_body<CHSI>(zs, Ws, bq, Qo, LOG2E, b, n0, wid, lr, q);
    } else {
        constexpr int WST = CMSI + 8;
        float* zs  = sm;
        float* Wks = sm + CMSI * ZST;
        float* Wvs = Wks + COUT * WST;
        const uint32_t zsb = smem_to_u32(zs);
        const uint32_t wkb = smem_to_u32(Wks);
        const uint32_t wvb = smem_to_u32(Wvs);
        const float* zb = zmsi + (size_t)b * CMSI * NPIX + n0;
        for (int id = tid; id < CMSI * 16; id += NTHR) {
            int r = id >> 4, c = id & 15;
            cp16(zsb + r * (ZST * 4) + c * 16, zb + (size_t)r * NPIX + c * 4);
        }
        for (int id = tid; id < COUT * (CMSI / 4); id += NTHR) {
            int r = id / (CMSI / 4), c = id % (CMSI / 4);
            cp16(wkb + r * (WST * 4) + c * 16, Wk + (size_t)r * CMSI + c * 4);
            cp16(wvb + r * (WST * 4) + c * 16, Wv + (size_t)r * CMSI + c * 4);
        }
        CP_COMMIT(); CP_WAIT0();
        __syncthreads();
        proj_qk_body<CMSI>(zs, Wks, bk, Ko, 1.0f, b, n0, wid, lr, q);
        proj_v_body<CMSI>(zs, Wvs, bv, Vto, b, n0, wid, lr, q);
    }
}

// ======================= bf16 mma flash attention (l via ones-column MMA) =======================
__global__ void __launch_bounds__(NTHR, 2)
attn_mma()
{
    extern __shared__ char smem[];
    const uint32_t sb = smem_to_u32(smem);
    const int tid  = threadIdx.x;
    const int wid  = tid >> 5;
    const int lane = tid & 31;
    const int lr   = lane >> 2;
    const int q    = lane & 3;

    const int bi = blockIdx.x;
    const int s  = bi % SPLIT;
    const int it = (bi / SPLIT) % NIT;
    const int b  = bi / (SPLIT * NIT);
    const int i0 = it * TI;
    const int jb = s * JPC;

    const char* Qg = (const char*)(g_Qh  + ((size_t)b * NPIX + i0) * D);
    const char* Kg = (const char*)(g_Kh  + (size_t)b * NPIX * D);
    const char* Vg = (const char*)(g_Vth + (size_t)b * D * NPIX);

    cp_qk(sb + SQ,  Qg, 2048, tid);
    cp_qk(sb + SK0, Kg + (size_t)jb * 256, 1024, tid);
    cp_v (sb + SV0, Vg + (size_t)jb * 2, tid);
    CP_COMMIT();
    cp_qk(sb + SK1, Kg + (size_t)(jb + TJ) * 256, 1024, tid);
    cp_v (sb + SV1, Vg + (size_t)(jb + TJ) * 2, tid);
    CP_COMMIT();

    float oacc[64];
#pragma unroll
    for (int i = 0; i < 64; i++) oacc[i] = 0.f;
    float lacc[4] = {0.f, 0.f, 0.f, 0.f};   // l via ones-MMA: all cols equal

    const int rowbase = wid * 16;
    const int s8   = lane >> 3;
    const int r8   = lane & 7;
    const int s_lo = s8 & 1;
    const int s_hi = s8 >> 1;

    const uint32_t qbase = sb + SQ + (uint32_t)(rowbase + s_lo * 8 + r8) * 256;
    const uint32_t kbase = (uint32_t)(s_hi * 8 + r8) * 256;
    const uint32_t vbase = (uint32_t)(s_hi * 8 + r8) * 128;

    for (int t = 0; t < TJT; t++) {
        if (t == TJT - 1) CP_WAIT0(); else CP_WAIT1();
        __syncthreads();
        const uint32_t skb = sb + ((t & 1) ? SK1 : SK0) + kbase;
        const uint32_t svb = sb + ((t & 1) ? SV1 : SV0) + vbase;

        // ---- MMA1: rows[rowbase,+16) x keys[0,64), 8 k16 steps ----
        float sacc[32];
#pragma unroll
        for (int i = 0; i < 32; i++) sacc[i] = 0.f;

#pragma unroll
        for (int kk = 0; kk < 8; kk++) {
            const uint32_t ca = (uint32_t)((2 * kk + s_hi) ^ r8) << 4;
            const uint32_t cb = (uint32_t)((2 * kk + s_lo) ^ r8) << 4;
            uint32_t A[4];
            ldsm4(A, qbase + ca);
#pragma unroll
            for (int g = 0; g < 4; g++) {
                uint32_t B[4];
                ldsm4(B, skb + (uint32_t)g * 4096 + cb);
                mma16(sacc + (2 * g) * 4,     A, B);
                mma16(sacc + (2 * g + 1) * 4, A, B + 2);
            }
        }

        // ---- per k-quarter: exp2 -> pack -> l-MMA (B=ones) -> MMA2 ----
#pragma unroll
        for (int kk = 0; kk < 4; kk++) {
            float* sp = sacc + 8 * kk;
            uint32_t A[4];
            A[0] = pk2(ex2(sp[0]), ex2(sp[1]));
            A[1] = pk2(ex2(sp[2]), ex2(sp[3]));
            A[2] = pk2(ex2(sp[4]), ex2(sp[5]));
            A[3] = pk2(ex2(sp[6]), ex2(sp[7]));
            {
                const uint32_t ones = 0x3F803F80u;   // bf16x2 (1.0, 1.0)
                uint32_t Bo[2] = {ones, ones};
                mma16(lacc, A, Bo);                  // lacc cols all = rowsum(P)
            }
            const uint32_t cb = (uint32_t)((2 * kk + s_lo) ^ r8) << 4;
#pragma unroll
            for (int g = 0; g < 8; g++) {
                uint32_t B[4];
                ldsm4(B, svb + (uint32_t)g * 2048 + cb);
                mma16(oacc + (2 * g) * 4,     A, B);
                mma16(oacc + (2 * g + 1) * 4, A, B + 2);
            }
        }
        __syncthreads();

        if (t + 2 < TJT) {
            const int jn = jb + (t + 2) * TJ;
            cp_qk(((t & 1) ? sb + SK1 : sb + SK0), Kg + (size_t)jn * 256, 1024, tid);
            cp_v (((t & 1) ? sb + SV1 : sb + SV0), Vg + (size_t)jn * 2, tid);
            CP_COMMIT();
        }
    }

    // ---- epilogue: l directly from fragment (no shuffles); write partials ----
    if (q == 0) {
        g_lp[(size_t)bi * TI + rowbase + lr]     = lacc[0];
        g_lp[(size_t)bi * TI + rowbase + lr + 8] = lacc[2];
    }
#pragma unroll
    for (int nn = 0; nn < 16; nn++) {
        const int c = nn * 8 + 2 * q;
        const int row0 = rowbase + lr;
        *(float2*)(g_Op + ((size_t)bi * TI + row0) * D + c) =
            make_float2(oacc[nn * 4 + 0], oacc[nn * 4 + 1]);
        *(float2*)(g_Op + ((size_t)bi * TI + row0 + 8) * D + c) =
            make_float2(oacc[nn * 4 + 2], oacc[nn * 4 + 3]);
    }
}

// ======================= split combine (unchanged) =======================
__global__ void __launch_bounds__(NTHR)
combine_kernel(const float* __restrict__ zhsi, const float* __restrict__ gammap,
               float* __restrict__ outp)
{
    __shared__ float sacc[32 * 129];
    __shared__ float rinv[TI];

    const int part = blockIdx.x & 3;
    const int blk  = blockIdx.x >> 2;
    const int b  = blk / NIT;
    const int i0 = (blk % NIT) * TI;
    const float g = *gammap;
    const int base = blk * SPLIT;
    const int tid = threadIdx.x;

    if (tid < TI) {
        float sl = 0.f;
#pragma unroll
        for (int sp = 0; sp < SPLIT; sp++)
            sl += g_lp[(size_t)(base + sp) * TI + tid];
        rinv[tid] = 1.0f / sl;
    }

#pragma unroll
    for (int k = 0; k < 4; k++) {
        const int f  = tid + NTHR * k;
        const int r  = f >> 3;
        const int c4 = f & 7;
        float4 a = make_float4(0.f, 0.f, 0.f, 0.f);
#pragma unroll
        for (int sp = 0; sp < SPLIT; sp++) {
            const float4* src = (const float4*)(g_Op
                + ((size_t)(base + sp) * TI + r) * D + part * 32);
            float4 v = __ldg(src + c4);
            a.x += v.x; a.y += v.y; a.z += v.z; a.w += v.w;
        }
        const int c = c4 * 4;
        sacc[(c + 0) * 129 + r] = a.x;
        sacc[(c + 1) * 129 + r] = a.y;
        sacc[(c + 2) * 129 + r] = a.z;
        sacc[(c + 3) * 129 + r] = a.w;
    }
    __syncthreads();

    for (int idx = tid; idx < 32 * TI; idx += NTHR) {
        const int c = idx >> 7;
        const int r = idx & 127;
        const size_t o = ((size_t)b * D + part * 32 + c) * NPIX + i0 + r;
        outp[o] = g * sacc[c * 129 + r] * rinv[r] + zhsi[o];
    }
}

// ======================= launch =======================
extern "C" void kernel_launch(void* const* d_in, const int* in_sizes, int n_in,
                              void* d_out, int out_size)
{
    const float* z_hsi = (const float*)d_in[0];
    const float* z_msi = (const float*)d_in[1];
    const float* Wq    = (const float*)d_in[2];
    const float* bq    = (const float*)d_in[3];
    const float* Wk    = (const float*)d_in[4];
    const float* bk    = (const float*)d_in[5];
    const float* Wv    = (const float*)d_in[6];
    const float* bv    = (const float*)d_in[7];
    const float* gamma = (const float*)d_in[8];
    float* out = (float*)d_out;

    __nv_bfloat16 *Qp, *Kp, *Vp;
    cudaGetSymbolAddress((void**)&Qp, g_Qh);
    cudaGetSymbolAddress((void**)&Kp, g_Kh);
    cudaGetSymbolAddress((void**)&Vp, g_Vth);

    const int smem_proj = (CHSI * ZST + COUT * (CHSI + 8)) * 4;  // 106496

    cudaFuncSetAttribute(proj_fused,
                         cudaFuncAttributeMaxDynamicSharedMemorySize, smem_proj);
    cudaFuncSetAttribute(attn_mma,
                         cudaFuncAttributeMaxDynamicSharedMemorySize, SM_TOTAL);

    dim3 pg(B_ * (NPIX / 64), 2);   // (200, 2)
    proj_fused<<<pg, NTHR, smem_proj>>>(z_hsi, Wq, bq, z_msi, Wk, bk, Wv, bv,
                                        Qp, Kp, Vp);

    attn_mma<<<B_ * NIT * SPLIT, NTHR, SM_TOTAL>>>();

    combine_kernel<<<B_ * NIT * 4, NTHR>>>(z_hsi, gamma, out);
}